// round 9
// baseline (speedup 1.0000x reference)
#include <cuda_runtime.h>

// out = joints @ R + t, R = RX(roll) @ RY(pitch) @ RZ(yaw)
// R rows (row i multiplies p[i], since result is p @ R):
//   r0 = [ cp*cy,            -cp*sy,            sp    ]
//   r1 = [ cr*sy + sr*sp*cy,  cr*cy - sr*sp*sy, -sr*cp]
//   r2 = [ sr*sy - cr*sp*cy,  sr*cy + cr*sp*sy,  cr*cp]

struct Rot {
    float r00, r01, r02;
    float r10, r11, r12;
    float r20, r21, r22;
    float tx, ty, tz;
};

__device__ __forceinline__ Rot make_rot(const float* __restrict__ ori,
                                        const float* __restrict__ trs) {
    float sr, cr, sp, cp, sy, cy;
    sincosf(ori[0], &sr, &cr);
    sincosf(ori[1], &sp, &cp);
    sincosf(ori[2], &sy, &cy);
    Rot R;
    R.r00 = cp * cy;                R.r01 = -cp * sy;               R.r02 = sp;
    R.r10 = cr * sy + sr * sp * cy; R.r11 = cr * cy - sr * sp * sy; R.r12 = -sr * cp;
    R.r20 = sr * sy - cr * sp * cy; R.r21 = sr * cy + cr * sp * sy; R.r22 = cr * cp;
    R.tx = trs[0]; R.ty = trs[1]; R.tz = trs[2];
    return R;
}

__device__ __forceinline__ void xform(const Rot& R, float x, float y, float z,
                                      float& ox, float& oy, float& oz) {
    ox = fmaf(x, R.r00, fmaf(y, R.r10, fmaf(z, R.r20, R.tx)));
    oy = fmaf(x, R.r01, fmaf(y, R.r11, fmaf(z, R.r21, R.ty)));
    oz = fmaf(x, R.r02, fmaf(y, R.r12, fmaf(z, R.r22, R.tz)));
}

// Block = 256 threads, handles 768 contiguous float4s (= 1024 points).
// Global loads/stores fully coalesced; point regrouping happens in smem.
// __launch_bounds__(256, 8): cap regs at 32 -> 8 CTAs/SM (R2 ran 6/SM @39r).
__global__ void __launch_bounds__(256, 8)
transform_smem(const float4* __restrict__ in, float4* __restrict__ out,
               const float* __restrict__ ori, const float* __restrict__ trs,
               int ntiles, int n_pts) {
    const int t   = threadIdx.x;
    const int bid = blockIdx.x;

    if (bid >= ntiles) {
        // Tail block: scalar path for points beyond the full tiles.
        const int start = ntiles * 1024;
        const Rot R = make_rot(ori, trs);
        const float* fin = (const float*)in;
        float* fout = (float*)out;
        for (int p = start + t; p < n_pts; p += 256) {
            long o = 3L * p;
            float x = fin[o], y = fin[o + 1], z = fin[o + 2];
            float ox, oy, oz;
            xform(R, x, y, z, ox, oy, oz);
            fout[o] = ox; fout[o + 1] = oy; fout[o + 2] = oz;
        }
        return;
    }

    __shared__ float4 s[768];
    const long base = (long)bid * 768;

    // Coalesced loads: warp lanes hit consecutive float4s (4 lines / LDG).
    float4 l0 = in[base + t];
    float4 l1 = in[base + t + 256];
    float4 l2 = in[base + t + 512];

    // Trig overlaps the loads (MUFU, independent).
    const Rot R = make_rot(ori, trs);

    s[t]       = l0;
    s[t + 256] = l1;
    s[t + 512] = l2;
    __syncthreads();

    // Private 3 float4s = 4 points. 48B stride -> conflict-free LDS.128.
    float4 a = s[3 * t + 0];
    float4 b = s[3 * t + 1];
    float4 c = s[3 * t + 2];

    float4 oa, ob, oc;
    xform(R, a.x, a.y, a.z, oa.x, oa.y, oa.z);
    xform(R, a.w, b.x, b.y, oa.w, ob.x, ob.y);
    xform(R, b.z, b.w, c.x, ob.z, ob.w, oc.x);
    xform(R, c.y, c.z, c.w, oc.y, oc.z, oc.w);

    s[3 * t + 0] = oa;
    s[3 * t + 1] = ob;
    s[3 * t + 2] = oc;
    __syncthreads();

    // Coalesced stores.
    out[base + t]       = s[t];
    out[base + t + 256] = s[t + 256];
    out[base + t + 512] = s[t + 512];
}

extern "C" void kernel_launch(void* const* d_in, const int* in_sizes, int n_in,
                              void* d_out, int out_size) {
    const float* joints = (const float*)d_in[0];
    const float* ori    = (const float*)d_in[1];
    const float* trs    = (const float*)d_in[2];
    float* out = (float*)d_out;

    const int n_floats = in_sizes[0];
    const int n_points = n_floats / 3;

    // Each full tile consumes 3072 floats (1024 points).
    const int ntiles = n_floats / 3072;               // 13780 exact for this shape
    const int tail_pts = n_points - ntiles * 1024;

    const int grid = ntiles + (tail_pts > 0 ? 1 : 0);
    if (grid > 0) {
        transform_smem<<<grid, 256>>>((const float4*)joints, (float4*)out,
                                      ori, trs, ntiles, n_points);
    }
}